// round 11
// baseline (speedup 1.0000x reference)
#include <cuda_runtime.h>
#include <cuda_bf16.h>
#include <cstdint>

#define NB 8
#define NC 256
#define NHW 4096
#define ND 32

typedef unsigned long long ull;

// Static device scratch
__device__ __nv_bfloat16 g_Qb[NB][NHW][ND];    // q * log2(e), [b][n][d] bf16
__device__ __nv_bfloat16 g_Kb[NB][NHW][ND];    // [b][n][d] bf16
__device__ __nv_bfloat16 g_Vb[NB][NC][NHW];    // [b][e][n] bf16

// ---------------------------------------------------------------------------
// helpers
// ---------------------------------------------------------------------------
__device__ __forceinline__ uint32_t smem_u32(const void* p) {
    uint32_t a;
    asm("{ .reg .u64 t; cvta.to.shared.u64 t, %1; cvt.u32.u64 %0, t; }"
        : "=r"(a) : "l"(p));
    return a;
}
__device__ __forceinline__ float fexp2(float v) {
    float r; asm("ex2.approx.ftz.f32 %0, %1;" : "=f"(r) : "f"(v)); return r;
}
// d = {hi, lo} packed bf16x2
__device__ __forceinline__ uint32_t pack_bf16(float hi, float lo) {
    uint32_t r; asm("cvt.rn.bf16x2.f32 %0, %1, %2;" : "=r"(r) : "f"(hi), "f"(lo));
    return r;
}
__device__ __forceinline__ void mma_bf16(float c[4], const uint32_t a[4],
                                         uint32_t b0, uint32_t b1) {
    asm volatile(
        "mma.sync.aligned.m16n8k16.row.col.f32.bf16.bf16.f32 "
        "{%0,%1,%2,%3}, {%4,%5,%6,%7}, {%8,%9}, {%0,%1,%2,%3};"
        : "+f"(c[0]), "+f"(c[1]), "+f"(c[2]), "+f"(c[3])
        : "r"(a[0]), "r"(a[1]), "r"(a[2]), "r"(a[3]), "r"(b0), "r"(b1));
}
__device__ __forceinline__ void ldmx4(uint32_t r[4], uint32_t a) {
    asm volatile("ldmatrix.sync.aligned.m8n8.x4.shared.b16 {%0,%1,%2,%3}, [%4];"
        : "=r"(r[0]), "=r"(r[1]), "=r"(r[2]), "=r"(r[3]) : "r"(a));
}
__device__ __forceinline__ void ldmx4t(uint32_t r[4], uint32_t a) {
    asm volatile("ldmatrix.sync.aligned.m8n8.x4.trans.shared.b16 {%0,%1,%2,%3}, [%4];"
        : "=r"(r[0]), "=r"(r[1]), "=r"(r[2]), "=r"(r[3]) : "r"(a));
}
__device__ __forceinline__ void cpa16(uint32_t s, const void* g) {
    asm volatile("cp.async.cg.shared.global [%0], [%1], 16;"
                 :: "r"(s), "l"(__cvta_generic_to_global(g)) : "memory");
}
#define CP_COMMIT() asm volatile("cp.async.commit_group;" ::: "memory")
#define CP_WAIT1()  asm volatile("cp.async.wait_group 1;" ::: "memory")
#define CP_WAIT0()  asm volatile("cp.async.wait_group 0;" ::: "memory")

// ============================================================================
// Kernel A: fused QKV projection, bf16 tensor cores (unchanged, ~15us).
// ============================================================================
#define QW_PITCH 528
#define OFF_W 0
#define OFF_BIAS 33792
#define OFF_X 34048
#define QKV_SMEM2 50944

__global__ __launch_bounds__(256) void qkv_kernel(
    const float* __restrict__ x,
    const float* __restrict__ Wq, const float* __restrict__ bq,
    const float* __restrict__ Wk, const float* __restrict__ bk,
    const float* __restrict__ Wv, const float* __restrict__ bv)
{
    extern __shared__ char sm[];
    const uint32_t sb = smem_u32(sm);
    const int b = blockIdx.z;
    const int oc0 = blockIdx.y * 64;
    const int n0 = blockIdx.x * 256;
    const int t = threadIdx.x, wid = t >> 5, lane = t & 31;
    const int wOC = wid & 1, wN = wid >> 1;
    const int r = lane >> 2, tq = lane & 3;

    #pragma unroll
    for (int l = 0; l < 16; l++) {
        int idx = t + l * 256;
        int row = idx >> 6, c4 = idx & 63;
        const float* src;
        if (oc0 == 0) src = (row < 32) ? &Wq[row * 256 + c4 * 4]
                                       : &Wk[(row - 32) * 256 + c4 * 4];
        else          src = &Wv[(oc0 - 64 + row) * 256 + c4 * 4];
        float4 w = *(const float4*)src;
        *(uint2*)(sm + OFF_W + row * QW_PITCH + c4 * 8) =
            make_uint2(pack_bf16(w.y, w.x), pack_bf16(w.w, w.z));
    }
    if (t < 64) {
        float bias;
        if (oc0 == 0) bias = (t < 32) ? bq[t] : bk[t - 32];
        else          bias = bv[oc0 - 64 + t];
        ((float*)(sm + OFF_BIAS))[t] = bias;
    }

    float acc[2][8][4];
    #pragma unroll
    for (int m = 0; m < 2; m++)
        #pragma unroll
        for (int j = 0; j < 8; j++)
            #pragma unroll
            for (int q = 0; q < 4; q++) acc[m][j][q] = 0.f;

    float4 xr[8];
    #pragma unroll
    for (int l = 0; l < 8; l++) {
        int idx = t + l * 256;
        int cc = idx >> 6, n4 = idx & 63;
        xr[l] = *(const float4*)&x[(b * NC + cc) * NHW + n0 + n4 * 4];
    }

    for (int ch = 0; ch < 8; ch++) {
        __syncthreads();
        #pragma unroll
        for (int l = 0; l < 8; l++) {
            int idx = t + l * 256;
            int cc = idx >> 6, n4 = idx & 63;
            *(uint2*)(sm + OFF_X + cc * QW_PITCH + n4 * 8) =
                make_uint2(pack_bf16(xr[l].y, xr[l].x), pack_bf16(xr[l].w, xr[l].z));
        }
        __syncthreads();
        if (ch + 1 < 8) {
            int c0n = (ch + 1) * 32;
            #pragma unroll
            for (int l = 0; l < 8; l++) {
                int idx = t + l * 256;
                int cc = idx >> 6, n4 = idx & 63;
                xr[l] = *(const float4*)&x[(b * NC + c0n + cc) * NHW + n0 + n4 * 4];
            }
        }
        #pragma unroll
        for (int ks = 0; ks < 2; ks++) {
            const int cb = ks * 16;
            uint32_t a0[4], a1[4];
            uint32_t wadr = sb + OFF_W + (wOC * 32 + (lane & 15)) * QW_PITCH
                            + (ch * 32 + cb) * 2 + (lane >> 4) * 16;
            ldmx4(a0, wadr);
            ldmx4(a1, wadr + 16 * QW_PITCH);
            uint32_t bt[4][4];
            #pragma unroll
            for (int nb = 0; nb < 4; nb++) {
                uint32_t xadr = sb + OFF_X
                    + (cb + (lane & 7) + ((lane >> 3) & 1) * 8) * QW_PITCH
                    + (wN * 64 + nb * 16 + (lane >> 4) * 8) * 2;
                ldmx4t(bt[nb], xadr);
            }
            #pragma unroll
            for (int nb = 0; nb < 4; nb++) {
                mma_bf16(acc[0][nb * 2],     a0, bt[nb][0], bt[nb][1]);
                mma_bf16(acc[0][nb * 2 + 1], a0, bt[nb][2], bt[nb][3]);
                mma_bf16(acc[1][nb * 2],     a1, bt[nb][0], bt[nb][1]);
                mma_bf16(acc[1][nb * 2 + 1], a1, bt[nb][2], bt[nb][3]);
            }
        }
    }
    __syncthreads();

    const float* bs = (const float*)(sm + OFF_BIAS);
    float bm[2][2];
    bm[0][0] = bs[wOC * 32 + r];      bm[0][1] = bs[wOC * 32 + r + 8];
    bm[1][0] = bs[wOC * 32 + 16 + r]; bm[1][1] = bs[wOC * 32 + 16 + r + 8];
    __syncthreads();

    if (oc0 == 0) {
        const float scl = (wOC == 0) ? 1.4426950408889634f : 1.0f;
        #pragma unroll
        for (int m = 0; m < 2; m++) {
            int oc_r0 = wOC * 32 + m * 16 + r;
            #pragma unroll
            for (int j = 0; j < 8; j++) {
                int n_ = wN * 64 + j * 8 + tq * 2;
                *(__nv_bfloat16*)(sm + n_ * 144 + oc_r0 * 2) =
                    __float2bfloat16((acc[m][j][0] + bm[m][0]) * scl);
                *(__nv_bfloat16*)(sm + (n_ + 1) * 144 + oc_r0 * 2) =
                    __float2bfloat16((acc[m][j][1] + bm[m][0]) * scl);
                *(__nv_bfloat16*)(sm + n_ * 144 + (oc_r0 + 8) * 2) =
                    __float2bfloat16((acc[m][j][2] + bm[m][1]) * scl);
                *(__nv_bfloat16*)(sm + (n_ + 1) * 144 + (oc_r0 + 8) * 2) =
                    __float2bfloat16((acc[m][j][3] + bm[m][1]) * scl);
            }
        }
        __syncthreads();
        #pragma unroll
        for (int l = 0; l < 4; l++) {
            int idx = t + l * 256;
            int nn = idx >> 2, c4 = idx & 3;
            *(float4*)&g_Qb[b][n0 + nn][c4 * 8] =
                *(const float4*)(sm + nn * 144 + c4 * 16);
            *(float4*)&g_Kb[b][n0 + nn][c4 * 8] =
                *(const float4*)(sm + nn * 144 + 64 + c4 * 16);
        }
    } else {
        #pragma unroll
        for (int m = 0; m < 2; m++) {
            int row0 = wOC * 32 + m * 16 + r;
            #pragma unroll
            for (int j = 0; j < 8; j++) {
                int n_ = wN * 64 + j * 8 + tq * 2;
                *(uint32_t*)(sm + row0 * 528 + n_ * 2) =
                    pack_bf16(acc[m][j][1] + bm[m][0], acc[m][j][0] + bm[m][0]);
                *(uint32_t*)(sm + (row0 + 8) * 528 + n_ * 2) =
                    pack_bf16(acc[m][j][3] + bm[m][1], acc[m][j][2] + bm[m][1]);
            }
        }
        __syncthreads();
        #pragma unroll
        for (int l = 0; l < 8; l++) {
            int idx = t + l * 256;
            int row = idx >> 5, n16 = idx & 31;
            *(float4*)&g_Vb[b][oc0 - 64 + row][n0 + n16 * 8] =
                *(const float4*)(sm + row * 528 + n16 * 16);
        }
    }
}

// ============================================================================
// Kernel B: flash attention with key-split P-exchange (no duplicated QK/exp).
// CTA 64q x 128E, 8 warps = 4 wM x 2 wE. Per iter (64 keys):
//   each warp: QK+exp+pack for ITS 32-key half (8 MMAs, 16 exp) -> STS pa ->
//   barrier -> LDS partner's pa -> PV over its 16q x 64E (32 MMAs).
// Every S element is computed/exp'd exactly ONCE per CTA.
// 3-stage K/V ring; rowsum halves merged at the end via smem.
// ============================================================================
#define OFF_Q 0
#define OFF_S 5120
#define STAGE_B 23552          // K 5120 + V 18432
#define OFF_PX  75776          // P exchange: 4 wM x 4 kstep x 32 lanes x 16B = 8KB
#define OFF_SUM 83968          // 2 x 64 f32
#define ATTN_SMEM_B 84480

__global__ __launch_bounds__(256, 2) void attn_kernel(
    const float* __restrict__ x,
    const float* __restrict__ gamma_p,
    float* __restrict__ out)
{
    extern __shared__ char smem[];
    const uint32_t sb = smem_u32(smem);
    const int t = threadIdx.x, wid = t >> 5, lane = t & 31;
    const int b = blockIdx.z;
    const int n0 = blockIdx.x * 64;
    const int e0 = blockIdx.y * 128;
    const int wM = wid & 3, wE = wid >> 2;
    const int r = lane >> 2, tq = lane & 3;

    const int krow = t >> 2, kch = t & 3;

    // ---- prologue: group0 = Q + tile0, group1 = tile1 ----
    cpa16(sb + OFF_Q + krow * 80 + kch * 16, &g_Qb[b][n0 + krow][kch * 8]);
    {
        uint32_t st = sb + OFF_S;
        cpa16(st + krow * 80 + kch * 16, &g_Kb[b][krow][kch * 8]);
        #pragma unroll
        for (int l = 0; l < 4; l++) {
            int c = t + l * 256;
            int e = c >> 3, ch8 = c & 7;
            cpa16(st + 5120 + e * 144 + ch8 * 16, &g_Vb[b][e0 + e][ch8 * 8]);
        }
    }
    CP_COMMIT();
    {
        uint32_t st = sb + OFF_S + STAGE_B;
        cpa16(st + krow * 80 + kch * 16, &g_Kb[b][64 + krow][kch * 8]);
        #pragma unroll
        for (int l = 0; l < 4; l++) {
            int c = t + l * 256;
            int e = c >> 3, ch8 = c & 7;
            cpa16(st + 5120 + e * 144 + ch8 * 16, &g_Vb[b][e0 + e][64 + ch8 * 8]);
        }
    }
    CP_COMMIT();
    CP_WAIT1();
    __syncthreads();

    // persistent Q fragments
    uint32_t qa[2][4];
    {
        uint32_t qaddr = sb + OFF_Q + (wM * 16 + (lane & 15)) * 80 + (lane >> 4) * 16;
        ldmx4(qa[0], qaddr);
        ldmx4(qa[1], qaddr + 32);
    }
    const uint32_t k_off = (lane & 7) * 80 + (lane >> 3) * 16;
    const uint32_t v_off = (wE * 64 + (lane & 7)) * 144 + (lane >> 3) * 16;
    // P exchange slots: [wM][kstep global][lane] x 16B
    const uint32_t px_base = sb + OFF_PX + (wM * 4 * 32 + lane) * 16;
    const int g_own = wE * 2;            // own global k-steps: g_own, g_own+1
    const int g_oth = 2 - wE * 2;        // partner's

    float o[8][4];
    #pragma unroll
    for (int tn = 0; tn < 8; tn++)
        #pragma unroll
        for (int j = 0; j < 4; j++) o[tn][j] = 0.f;
    float sum0 = 0.f, sum1 = 0.f;

    int s_cur = 0, s_pf = 2;
    for (int i = 0; i < 64; i++) {
        if (i) {
            if (i >= 63) { CP_WAIT0(); } else { CP_WAIT1(); }
            __syncthreads();               // bar1: tile i ready; PX slot free
        }
        if (i + 2 < 64) {                  // prefetch tile i+2
            int m0 = (i + 2) * 64;
            uint32_t st = sb + OFF_S + s_pf * STAGE_B;
            cpa16(st + krow * 80 + kch * 16, &g_Kb[b][m0 + krow][kch * 8]);
            #pragma unroll
            for (int l = 0; l < 4; l++) {
                int c = t + l * 256;
                int e = c >> 3, ch8 = c & 7;
                cpa16(st + 5120 + e * 144 + ch8 * 16, &g_Vb[b][e0 + e][m0 + ch8 * 8]);
            }
            CP_COMMIT();
        }

        const uint32_t kb = sb + OFF_S + s_cur * STAGE_B;
        const uint32_t vb = kb + 5120;

        // ---- QK + exp + pack for OWN 32-key half only ----
        uint32_t pa[4][4];
        #pragma unroll
        for (int g = 0; g < 2; g++) {      // local k-step
            const int tn0 = wE * 4 + g * 2;
            uint32_t kf[4];
            float sa[4], sbv[4];
            ldmx4(kf, kb + tn0 * 640 + k_off);
            sa[0] = sa[1] = sa[2] = sa[3] = 0.f;
            mma_bf16(sa, qa[0], kf[0], kf[1]);
            mma_bf16(sa, qa[1], kf[2], kf[3]);
            ldmx4(kf, kb + (tn0 + 1) * 640 + k_off);
            sbv[0] = sbv[1] = sbv[2] = sbv[3] = 0.f;
            mma_bf16(sbv, qa[0], kf[0], kf[1]);
            mma_bf16(sbv, qa[1], kf[2], kf[3]);

            float p0 = fexp2(sa[0]),  p1 = fexp2(sa[1]);
            float p2 = fexp2(sa[2]),  p3 = fexp2(sa[3]);
            float q0 = fexp2(sbv[0]), q1 = fexp2(sbv[1]);
            float q2 = fexp2(sbv[2]), q3 = fexp2(sbv[3]);
            sum0 += p0 + p1 + q0 + q1;
            sum1 += p2 + p3 + q2 + q3;
            const int gg = g_own + g;
            pa[gg][0] = pack_bf16(p1, p0);
            pa[gg][1] = pack_bf16(p3, p2);
            pa[gg][2] = pack_bf16(q1, q0);
            pa[gg][3] = pack_bf16(q3, q2);
        }
        // publish own halves
        *(uint4*)(smem + (px_base - sb) + (g_own)     * 512) =
            make_uint4(pa[g_own][0], pa[g_own][1], pa[g_own][2], pa[g_own][3]);
        *(uint4*)(smem + (px_base - sb) + (g_own + 1) * 512) =
            make_uint4(pa[g_own + 1][0], pa[g_own + 1][1],
                       pa[g_own + 1][2], pa[g_own + 1][3]);
        __syncthreads();                   // bar2: P exchange visible
        // fetch partner halves
        {
            uint4 u0 = *(const uint4*)(smem + (px_base - sb) + (g_oth)     * 512);
            uint4 u1 = *(const uint4*)(smem + (px_base - sb) + (g_oth + 1) * 512);
            pa[g_oth][0] = u0.x; pa[g_oth][1] = u0.y;
            pa[g_oth][2] = u0.z; pa[g_oth][3] = u0.w;
            pa[g_oth + 1][0] = u1.x; pa[g_oth + 1][1] = u1.y;
            pa[g_oth + 1][2] = u1.z; pa[g_oth + 1][3] = u1.w;
        }

        // ---- O += P V (full 64 keys) ----
        #pragma unroll
        for (int eb = 0; eb < 8; eb++) {
            uint32_t v0[4], v1[4];
            ldmx4(v0, vb + v_off + eb * 1152);
            ldmx4(v1, vb + v_off + eb * 1152 + 64);
            mma_bf16(o[eb], pa[0], v0[0], v0[1]);
            mma_bf16(o[eb], pa[1], v0[2], v0[3]);
            mma_bf16(o[eb], pa[2], v1[0], v1[1]);
            mma_bf16(o[eb], pa[3], v1[2], v1[3]);
        }

        s_cur = (s_cur == 2) ? 0 : s_cur + 1;
        s_pf  = (s_pf == 2)  ? 0 : s_pf + 1;
    }

    // ---- merge rowsum halves across wE partners ----
    sum0 += __shfl_xor_sync(0xffffffffu, sum0, 1);
    sum0 += __shfl_xor_sync(0xffffffffu, sum0, 2);
    sum1 += __shfl_xor_sync(0xffffffffu, sum1, 1);
    sum1 += __shfl_xor_sync(0xffffffffu, sum1, 2);
    float* sums = (float*)(smem + OFF_SUM);   // [2][64]
    __syncthreads();
    if (tq == 0) {
        sums[wE * 64 + wM * 16 + r]     = sum0;
        sums[wE * 64 + wM * 16 + r + 8] = sum1;
    }
    __syncthreads();
    const float g = gamma_p[0];
    const float sc0 = g / (sums[wM * 16 + r]     + sums[64 + wM * 16 + r]);
    const float sc1 = g / (sums[wM * 16 + r + 8] + sums[64 + wM * 16 + r + 8]);

    __syncthreads();
    float* os = (float*)smem;                 // [64][133]
    #pragma unroll
    for (int tn = 0; tn < 8; tn++) {
        int e = wE * 64 + tn * 8 + 2 * tq;
        os[(wM * 16 + r) * 133 + e]         = o[tn][0] * sc0;
        os[(wM * 16 + r) * 133 + e + 1]     = o[tn][1] * sc0;
        os[(wM * 16 + r + 8) * 133 + e]     = o[tn][2] * sc1;
        os[(wM * 16 + r + 8) * 133 + e + 1] = o[tn][3] * sc1;
    }
    __syncthreads();
    #pragma unroll 8
    for (int l = 0; l < 32; l++) {
        int idx = t + l * 256;
        int n = idx & 63, e = idx >> 6;
        int gi = (b * NC + e0 + e) * NHW + n0 + n;
        out[gi] = os[n * 133 + e] + x[gi];
    }
}

// ============================================================================
extern "C" void kernel_launch(void* const* d_in, const int* in_sizes, int n_in,
                              void* d_out, int out_size) {
    (void)in_sizes; (void)n_in; (void)out_size;
    const float* x     = (const float*)d_in[0];
    const float* Wq    = (const float*)d_in[1];
    const float* bq    = (const float*)d_in[2];
    const float* Wk    = (const float*)d_in[3];
    const float* bk    = (const float*)d_in[4];
    const float* Wv    = (const float*)d_in[5];
    const float* bv    = (const float*)d_in[6];
    const float* gamma = (const float*)d_in[7];
    float* out = (float*)d_out;

    cudaFuncSetAttribute(qkv_kernel,
                         cudaFuncAttributeMaxDynamicSharedMemorySize, QKV_SMEM2);
    cudaFuncSetAttribute(attn_kernel,
                         cudaFuncAttributeMaxDynamicSharedMemorySize, ATTN_SMEM_B);

    dim3 gA(16, 5, NB);
    qkv_kernel<<<gA, 256, QKV_SMEM2>>>(x, Wq, bq, Wk, bk, Wv, bv);

    dim3 gB(64, 2, NB);
    attn_kernel<<<gB, 256, ATTN_SMEM_B>>>(x, gamma, out);
}

// round 12
// speedup vs baseline: 1.2935x; 1.2935x over previous
#include <cuda_runtime.h>
#include <cuda_bf16.h>
#include <cstdint>

#define NB 8
#define NC 256
#define NHW 4096
#define ND 32

typedef unsigned long long ull;

// Static device scratch
__device__ __nv_bfloat16 g_Qb[NB][NHW][ND];    // q * log2(e), [b][n][d] bf16
__device__ __nv_bfloat16 g_Kb[NB][NHW][ND];    // [b][n][d] bf16
__device__ __nv_bfloat16 g_Vb[NB][NC][NHW];    // [b][e][n] bf16

// ---------------------------------------------------------------------------
// helpers
// ---------------------------------------------------------------------------
__device__ __forceinline__ uint32_t smem_u32(const void* p) {
    uint32_t a;
    asm("{ .reg .u64 t; cvta.to.shared.u64 t, %1; cvt.u32.u64 %0, t; }"
        : "=r"(a) : "l"(p));
    return a;
}
__device__ __forceinline__ float fexp2(float v) {
    float r; asm("ex2.approx.ftz.f32 %0, %1;" : "=f"(r) : "f"(v)); return r;
}
// d = {hi, lo} packed bf16x2
__device__ __forceinline__ uint32_t pack_bf16(float hi, float lo) {
    uint32_t r; asm("cvt.rn.bf16x2.f32 %0, %1, %2;" : "=r"(r) : "f"(hi), "f"(lo));
    return r;
}
__device__ __forceinline__ void mma_bf16(float c[4], const uint32_t a[4],
                                         uint32_t b0, uint32_t b1) {
    asm volatile(
        "mma.sync.aligned.m16n8k16.row.col.f32.bf16.bf16.f32 "
        "{%0,%1,%2,%3}, {%4,%5,%6,%7}, {%8,%9}, {%0,%1,%2,%3};"
        : "+f"(c[0]), "+f"(c[1]), "+f"(c[2]), "+f"(c[3])
        : "r"(a[0]), "r"(a[1]), "r"(a[2]), "r"(a[3]), "r"(b0), "r"(b1));
}
__device__ __forceinline__ void ldmx4(uint32_t r[4], uint32_t a) {
    asm volatile("ldmatrix.sync.aligned.m8n8.x4.shared.b16 {%0,%1,%2,%3}, [%4];"
        : "=r"(r[0]), "=r"(r[1]), "=r"(r[2]), "=r"(r[3]) : "r"(a));
}
__device__ __forceinline__ void ldmx4t(uint32_t r[4], uint32_t a) {
    asm volatile("ldmatrix.sync.aligned.m8n8.x4.trans.shared.b16 {%0,%1,%2,%3}, [%4];"
        : "=r"(r[0]), "=r"(r[1]), "=r"(r[2]), "=r"(r[3]) : "r"(a));
}
__device__ __forceinline__ void cpa16(uint32_t s, const void* g) {
    asm volatile("cp.async.cg.shared.global [%0], [%1], 16;"
                 :: "r"(s), "l"(__cvta_generic_to_global(g)) : "memory");
}
#define CP_COMMIT() asm volatile("cp.async.commit_group;" ::: "memory")
#define CP_WAIT2()  asm volatile("cp.async.wait_group 2;" ::: "memory")
#define CP_WAIT1()  asm volatile("cp.async.wait_group 1;" ::: "memory")
#define CP_WAIT0()  asm volatile("cp.async.wait_group 0;" ::: "memory")

// ============================================================================
// Kernel A: fused QKV projection, bf16 tensor cores (unchanged, ~15us).
// ============================================================================
#define QW_PITCH 528
#define OFF_W 0
#define OFF_BIAS 33792
#define OFF_X 34048
#define QKV_SMEM2 50944

__global__ __launch_bounds__(256) void qkv_kernel(
    const float* __restrict__ x,
    const float* __restrict__ Wq, const float* __restrict__ bq,
    const float* __restrict__ Wk, const float* __restrict__ bk,
    const float* __restrict__ Wv, const float* __restrict__ bv)
{
    extern __shared__ char sm[];
    const uint32_t sb = smem_u32(sm);
    const int b = blockIdx.z;
    const int oc0 = blockIdx.y * 64;
    const int n0 = blockIdx.x * 256;
    const int t = threadIdx.x, wid = t >> 5, lane = t & 31;
    const int wOC = wid & 1, wN = wid >> 1;
    const int r = lane >> 2, tq = lane & 3;

    #pragma unroll
    for (int l = 0; l < 16; l++) {
        int idx = t + l * 256;
        int row = idx >> 6, c4 = idx & 63;
        const float* src;
        if (oc0 == 0) src = (row < 32) ? &Wq[row * 256 + c4 * 4]
                                       : &Wk[(row - 32) * 256 + c4 * 4];
        else          src = &Wv[(oc0 - 64 + row) * 256 + c4 * 4];
        float4 w = *(const float4*)src;
        *(uint2*)(sm + OFF_W + row * QW_PITCH + c4 * 8) =
            make_uint2(pack_bf16(w.y, w.x), pack_bf16(w.w, w.z));
    }
    if (t < 64) {
        float bias;
        if (oc0 == 0) bias = (t < 32) ? bq[t] : bk[t - 32];
        else          bias = bv[oc0 - 64 + t];
        ((float*)(sm + OFF_BIAS))[t] = bias;
    }

    float acc[2][8][4];
    #pragma unroll
    for (int m = 0; m < 2; m++)
        #pragma unroll
        for (int j = 0; j < 8; j++)
            #pragma unroll
            for (int q = 0; q < 4; q++) acc[m][j][q] = 0.f;

    float4 xr[8];
    #pragma unroll
    for (int l = 0; l < 8; l++) {
        int idx = t + l * 256;
        int cc = idx >> 6, n4 = idx & 63;
        xr[l] = *(const float4*)&x[(b * NC + cc) * NHW + n0 + n4 * 4];
    }

    for (int ch = 0; ch < 8; ch++) {
        __syncthreads();
        #pragma unroll
        for (int l = 0; l < 8; l++) {
            int idx = t + l * 256;
            int cc = idx >> 6, n4 = idx & 63;
            *(uint2*)(sm + OFF_X + cc * QW_PITCH + n4 * 8) =
                make_uint2(pack_bf16(xr[l].y, xr[l].x), pack_bf16(xr[l].w, xr[l].z));
        }
        __syncthreads();
        if (ch + 1 < 8) {
            int c0n = (ch + 1) * 32;
            #pragma unroll
            for (int l = 0; l < 8; l++) {
                int idx = t + l * 256;
                int cc = idx >> 6, n4 = idx & 63;
                xr[l] = *(const float4*)&x[(b * NC + c0n + cc) * NHW + n0 + n4 * 4];
            }
        }
        #pragma unroll
        for (int ks = 0; ks < 2; ks++) {
            const int cb = ks * 16;
            uint32_t a0[4], a1[4];
            uint32_t wadr = sb + OFF_W + (wOC * 32 + (lane & 15)) * QW_PITCH
                            + (ch * 32 + cb) * 2 + (lane >> 4) * 16;
            ldmx4(a0, wadr);
            ldmx4(a1, wadr + 16 * QW_PITCH);
            uint32_t bt[4][4];
            #pragma unroll
            for (int nb = 0; nb < 4; nb++) {
                uint32_t xadr = sb + OFF_X
                    + (cb + (lane & 7) + ((lane >> 3) & 1) * 8) * QW_PITCH
                    + (wN * 64 + nb * 16 + (lane >> 4) * 8) * 2;
                ldmx4t(bt[nb], xadr);
            }
            #pragma unroll
            for (int nb = 0; nb < 4; nb++) {
                mma_bf16(acc[0][nb * 2],     a0, bt[nb][0], bt[nb][1]);
                mma_bf16(acc[0][nb * 2 + 1], a0, bt[nb][2], bt[nb][3]);
                mma_bf16(acc[1][nb * 2],     a1, bt[nb][0], bt[nb][1]);
                mma_bf16(acc[1][nb * 2 + 1], a1, bt[nb][2], bt[nb][3]);
            }
        }
    }
    __syncthreads();

    const float* bs = (const float*)(sm + OFF_BIAS);
    float bm[2][2];
    bm[0][0] = bs[wOC * 32 + r];      bm[0][1] = bs[wOC * 32 + r + 8];
    bm[1][0] = bs[wOC * 32 + 16 + r]; bm[1][1] = bs[wOC * 32 + 16 + r + 8];
    __syncthreads();

    if (oc0 == 0) {
        const float scl = (wOC == 0) ? 1.4426950408889634f : 1.0f;
        #pragma unroll
        for (int m = 0; m < 2; m++) {
            int oc_r0 = wOC * 32 + m * 16 + r;
            #pragma unroll
            for (int j = 0; j < 8; j++) {
                int n_ = wN * 64 + j * 8 + tq * 2;
                *(__nv_bfloat16*)(sm + n_ * 144 + oc_r0 * 2) =
                    __float2bfloat16((acc[m][j][0] + bm[m][0]) * scl);
                *(__nv_bfloat16*)(sm + (n_ + 1) * 144 + oc_r0 * 2) =
                    __float2bfloat16((acc[m][j][1] + bm[m][0]) * scl);
                *(__nv_bfloat16*)(sm + n_ * 144 + (oc_r0 + 8) * 2) =
                    __float2bfloat16((acc[m][j][2] + bm[m][1]) * scl);
                *(__nv_bfloat16*)(sm + (n_ + 1) * 144 + (oc_r0 + 8) * 2) =
                    __float2bfloat16((acc[m][j][3] + bm[m][1]) * scl);
            }
        }
        __syncthreads();
        #pragma unroll
        for (int l = 0; l < 4; l++) {
            int idx = t + l * 256;
            int nn = idx >> 2, c4 = idx & 3;
            *(float4*)&g_Qb[b][n0 + nn][c4 * 8] =
                *(const float4*)(sm + nn * 144 + c4 * 16);
            *(float4*)&g_Kb[b][n0 + nn][c4 * 8] =
                *(const float4*)(sm + nn * 144 + 64 + c4 * 16);
        }
    } else {
        #pragma unroll
        for (int m = 0; m < 2; m++) {
            int row0 = wOC * 32 + m * 16 + r;
            #pragma unroll
            for (int j = 0; j < 8; j++) {
                int n_ = wN * 64 + j * 8 + tq * 2;
                *(uint32_t*)(sm + row0 * 528 + n_ * 2) =
                    pack_bf16(acc[m][j][1] + bm[m][0], acc[m][j][0] + bm[m][0]);
                *(uint32_t*)(sm + (row0 + 8) * 528 + n_ * 2) =
                    pack_bf16(acc[m][j][3] + bm[m][1], acc[m][j][2] + bm[m][1]);
            }
        }
        __syncthreads();
        #pragma unroll
        for (int l = 0; l < 8; l++) {
            int idx = t + l * 256;
            int row = idx >> 5, n16 = idx & 31;
            *(float4*)&g_Vb[b][oc0 - 64 + row][n0 + n16 * 8] =
                *(const float4*)(sm + row * 528 + n16 * 16);
        }
    }
}

// ============================================================================
// Kernel B: flash attention with CROSS-ITERATION key-split P-exchange.
// CTA 64q x 128E, 8 warps = 4 wM x 2 wE. At iter i each warp:
//   - computes QK+exp+pack for ITS 32-key half of tile i+1 (4 MMAs x2, 16 exp)
//     and STS's the packed frags to pbuf[(i+1)&1];
//   - runs PV(i) with ALL P frags LDS'd from pbuf[i&1] (published at iter i-1,
//     fenced by this iteration's regular barrier — NO mid-iteration barrier).
// Every S element computed/exp'd exactly once per CTA. 40 MMA/warp-iter vs 48.
// K,V in separate cp.async commit groups; wait_group 1 guarantees K(i+1)+V(i).
// 3-stage K ring, 3-stage V ring, double-buffered P.
// ============================================================================
#define OFF_Q 0
#define OFF_K 5120             // 3 x 5120
#define OFF_V 20480            // 3 x 18432
#define OFF_PB 75776           // 2 x 8192
#define OFF_SUM 92160          // 2 x 64 f32
#define ATTN_SMEM_B 92672

__global__ __launch_bounds__(256, 2) void attn_kernel(
    const float* __restrict__ x,
    const float* __restrict__ gamma_p,
    float* __restrict__ out)
{
    extern __shared__ char smem[];
    const uint32_t sb = smem_u32(smem);
    const int t = threadIdx.x, wid = t >> 5, lane = t & 31;
    const int b = blockIdx.z;
    const int n0 = blockIdx.x * 64;
    const int e0 = blockIdx.y * 128;
    const int wM = wid & 3, wE = wid >> 2;
    const int r = lane >> 2, tq = lane & 3;

    const int krow = t >> 2, kch = t & 3;

    // ---- prologue: G0={Q,K0}  G1={V0,K1}  G2={V1} ----
    cpa16(sb + OFF_Q + krow * 80 + kch * 16, &g_Qb[b][n0 + krow][kch * 8]);
    cpa16(sb + OFF_K + krow * 80 + kch * 16, &g_Kb[b][krow][kch * 8]);
    CP_COMMIT();
    #pragma unroll
    for (int l = 0; l < 4; l++) {
        int c = t + l * 256;
        int e = c >> 3, ch8 = c & 7;
        cpa16(sb + OFF_V + e * 144 + ch8 * 16, &g_Vb[b][e0 + e][ch8 * 8]);
    }
    cpa16(sb + OFF_K + 5120 + krow * 80 + kch * 16, &g_Kb[b][64 + krow][kch * 8]);
    CP_COMMIT();
    #pragma unroll
    for (int l = 0; l < 4; l++) {
        int c = t + l * 256;
        int e = c >> 3, ch8 = c & 7;
        cpa16(sb + OFF_V + 18432 + e * 144 + ch8 * 16, &g_Vb[b][e0 + e][64 + ch8 * 8]);
    }
    CP_COMMIT();

    CP_WAIT2();                  // G0 done: Q + K0 resident
    __syncthreads();

    // persistent Q fragments
    uint32_t qa[2][4];
    {
        uint32_t qaddr = sb + OFF_Q + (wM * 16 + (lane & 15)) * 80 + (lane >> 4) * 16;
        ldmx4(qa[0], qaddr);
        ldmx4(qa[1], qaddr + 32);
    }
    const uint32_t k_off = (lane & 7) * 80 + (lane >> 3) * 16;
    const uint32_t v_off = (wE * 64 + (lane & 7)) * 144 + (lane >> 3) * 16;
    const uint32_t px_lane = (uint32_t)lane * 16;

    float o[8][4];
    #pragma unroll
    for (int tn = 0; tn < 8; tn++)
        #pragma unroll
        for (int j = 0; j < 4; j++) o[tn][j] = 0.f;
    float sum0 = 0.f, sum1 = 0.f;

    // ---- compute P(0) for own 32-key half, publish to pbuf0 ----
    #define COMPUTE_P_HALF(J)                                                     \
    {                                                                             \
        const uint32_t kb_ = sb + OFF_K + ((J) % 3) * 5120;                       \
        const uint32_t pb_ = sb + OFF_PB + ((J) & 1) * 8192;                      \
        _Pragma("unroll")                                                         \
        for (int g = 0; g < 2; g++) {                                             \
            const int tn0 = wE * 4 + g * 2;                                       \
            uint32_t kf[4];                                                       \
            float sa[4], sbv[4];                                                  \
            ldmx4(kf, kb_ + tn0 * 640 + k_off);                                   \
            sa[0] = sa[1] = sa[2] = sa[3] = 0.f;                                  \
            mma_bf16(sa, qa[0], kf[0], kf[1]);                                    \
            mma_bf16(sa, qa[1], kf[2], kf[3]);                                    \
            ldmx4(kf, kb_ + (tn0 + 1) * 640 + k_off);                             \
            sbv[0] = sbv[1] = sbv[2] = sbv[3] = 0.f;                              \
            mma_bf16(sbv, qa[0], kf[0], kf[1]);                                   \
            mma_bf16(sbv, qa[1], kf[2], kf[3]);                                   \
            float p0 = fexp2(sa[0]),  p1 = fexp2(sa[1]);                          \
            float p2 = fexp2(sa[2]),  p3 = fexp2(sa[3]);                          \
            float q0 = fexp2(sbv[0]), q1 = fexp2(sbv[1]);                         \
            float q2 = fexp2(sbv[2]), q3 = fexp2(sbv[3]);                         \
            sum0 += p0 + p1 + q0 + q1;                                            \
            sum1 += p2 + p3 + q2 + q3;                                            \
            *(uint4*)((char*)smem + (pb_ - sb)                                    \
                      + ((wM * 4 + wE * 2 + g) * 32) * 16 + px_lane) =            \
                make_uint4(pack_bf16(p1, p0), pack_bf16(p3, p2),                  \
                           pack_bf16(q1, q0), pack_bf16(q3, q2));                 \
        }                                                                         \
    }

    COMPUTE_P_HALF(0);

    for (int i = 0; i < 64; i++) {
        if (i < 63) { CP_WAIT1(); } else { CP_WAIT0(); }
        __syncthreads();               // V(i)+K(i+1) ready; P(i) exchange visible

        if (i + 2 < 64) {              // prefetch tile i+2: K group, then V group
            int m0 = (i + 2) * 64;
            cpa16(sb + OFF_K + ((i + 2) % 3) * 5120 + krow * 80 + kch * 16,
                  &g_Kb[b][m0 + krow][kch * 8]);
            CP_COMMIT();
            uint32_t vst = sb + OFF_V + ((i + 2) % 3) * 18432;
            #pragma unroll
            for (int l = 0; l < 4; l++) {
                int c = t + l * 256;
                int e = c >> 3, ch8 = c & 7;
                cpa16(vst + e * 144 + ch8 * 16, &g_Vb[b][e0 + e][m0 + ch8 * 8]);
            }
            CP_COMMIT();
        }

        if (i + 1 < 64) COMPUTE_P_HALF(i + 1);

        // ---- PV(i): all four P k-steps from pbuf[i&1] ----
        uint32_t pa[4][4];
        #pragma unroll
        for (int s = 0; s < 4; s++) {
            uint4 u = *(const uint4*)((char*)smem + OFF_PB + (i & 1) * 8192
                                      + ((wM * 4 + s) * 32) * 16 + px_lane);
            pa[s][0] = u.x; pa[s][1] = u.y; pa[s][2] = u.z; pa[s][3] = u.w;
        }
        const uint32_t vb = sb + OFF_V + (i % 3) * 18432;
        #pragma unroll
        for (int eb = 0; eb < 8; eb++) {
            uint32_t v0[4], v1[4];
            ldmx4(v0, vb + v_off + eb * 1152);
            ldmx4(v1, vb + v_off + eb * 1152 + 64);
            mma_bf16(o[eb], pa[0], v0[0], v0[1]);
            mma_bf16(o[eb], pa[1], v0[2], v0[3]);
            mma_bf16(o[eb], pa[2], v1[0], v1[1]);
            mma_bf16(o[eb], pa[3], v1[2], v1[3]);
        }
    }

    // ---- merge rowsum halves across wE partners ----
    sum0 += __shfl_xor_sync(0xffffffffu, sum0, 1);
    sum0 += __shfl_xor_sync(0xffffffffu, sum0, 2);
    sum1 += __shfl_xor_sync(0xffffffffu, sum1, 1);
    sum1 += __shfl_xor_sync(0xffffffffu, sum1, 2);
    float* sums = (float*)(smem + OFF_SUM);   // [2][64]
    __syncthreads();
    if (tq == 0) {
        sums[wE * 64 + wM * 16 + r]     = sum0;
        sums[wE * 64 + wM * 16 + r + 8] = sum1;
    }
    __syncthreads();
    const float g = gamma_p[0];
    const float sc0 = g / (sums[wM * 16 + r]     + sums[64 + wM * 16 + r]);
    const float sc1 = g / (sums[wM * 16 + r + 8] + sums[64 + wM * 16 + r + 8]);

    __syncthreads();
    float* os = (float*)smem;                 // [64][133]
    #pragma unroll
    for (int tn = 0; tn < 8; tn++) {
        int e = wE * 64 + tn * 8 + 2 * tq;
        os[(wM * 16 + r) * 133 + e]         = o[tn][0] * sc0;
        os[(wM * 16 + r) * 133 + e + 1]     = o[tn][1] * sc0;
        os[(wM * 16 + r + 8) * 133 + e]     = o[tn][2] * sc1;
        os[(wM * 16 + r + 8) * 133 + e + 1] = o[tn][3] * sc1;
    }
    __syncthreads();
    #pragma unroll 8
    for (int l = 0; l < 32; l++) {
        int idx = t + l * 256;
        int n = idx & 63, e = idx >> 6;
        int gi = (b * NC + e0 + e) * NHW + n0 + n;
        out[gi] = os[n * 133 + e] + x[gi];
    }
}

// ============================================================================
extern "C" void kernel_launch(void* const* d_in, const int* in_sizes, int n_in,
                              void* d_out, int out_size) {
    (void)in_sizes; (void)n_in; (void)out_size;
    const float* x     = (const float*)d_in[0];
    const float* Wq    = (const float*)d_in[1];
    const float* bq    = (const float*)d_in[2];
    const float* Wk    = (const float*)d_in[3];
    const float* bk    = (const float*)d_in[4];
    const float* Wv    = (const float*)d_in[5];
    const float* bv    = (const float*)d_in[6];
    const float* gamma = (const float*)d_in[7];
    float* out = (float*)d_out;

    cudaFuncSetAttribute(qkv_kernel,
                         cudaFuncAttributeMaxDynamicSharedMemorySize, QKV_SMEM2);
    cudaFuncSetAttribute(attn_kernel,
                         cudaFuncAttributeMaxDynamicSharedMemorySize, ATTN_SMEM_B);

    dim3 gA(16, 5, NB);
    qkv_kernel<<<gA, 256, QKV_SMEM2>>>(x, Wq, bq, Wk, bk, Wv, bv);

    dim3 gB(64, 2, NB);
    attn_kernel<<<gB, 256, ATTN_SMEM_B>>>(x, gamma, out);
}

// round 13
// speedup vs baseline: 1.4253x; 1.1019x over previous
#include <cuda_runtime.h>
#include <cuda_bf16.h>
#include <cstdint>

#define NB 8
#define NC 256
#define NHW 4096
#define ND 32

typedef unsigned long long ull;

// Static device scratch
__device__ __nv_bfloat16 g_Qb[NB][NHW][ND];    // q * log2(e), [b][n][d] bf16
__device__ __nv_bfloat16 g_Kb[NB][NHW][ND];    // [b][n][d] bf16
__device__ __nv_bfloat16 g_Vb[NB][NC][NHW];    // [b][e][n] bf16

// ---------------------------------------------------------------------------
// helpers
// ---------------------------------------------------------------------------
__device__ __forceinline__ uint32_t smem_u32(const void* p) {
    uint32_t a;
    asm("{ .reg .u64 t; cvta.to.shared.u64 t, %1; cvt.u32.u64 %0, t; }"
        : "=r"(a) : "l"(p));
    return a;
}
__device__ __forceinline__ float fexp2(float v) {
    float r; asm("ex2.approx.ftz.f32 %0, %1;" : "=f"(r) : "f"(v)); return r;
}
// d = {hi, lo} packed bf16x2
__device__ __forceinline__ uint32_t pack_bf16(float hi, float lo) {
    uint32_t r; asm("cvt.rn.bf16x2.f32 %0, %1, %2;" : "=r"(r) : "f"(hi), "f"(lo));
    return r;
}
__device__ __forceinline__ void mma_bf16(float c[4], const uint32_t a[4],
                                         uint32_t b0, uint32_t b1) {
    asm volatile(
        "mma.sync.aligned.m16n8k16.row.col.f32.bf16.bf16.f32 "
        "{%0,%1,%2,%3}, {%4,%5,%6,%7}, {%8,%9}, {%0,%1,%2,%3};"
        : "+f"(c[0]), "+f"(c[1]), "+f"(c[2]), "+f"(c[3])
        : "r"(a[0]), "r"(a[1]), "r"(a[2]), "r"(a[3]), "r"(b0), "r"(b1));
}
__device__ __forceinline__ void ldmx4(uint32_t r[4], uint32_t a) {
    asm volatile("ldmatrix.sync.aligned.m8n8.x4.shared.b16 {%0,%1,%2,%3}, [%4];"
        : "=r"(r[0]), "=r"(r[1]), "=r"(r[2]), "=r"(r[3]) : "r"(a));
}
__device__ __forceinline__ void ldmx4t(uint32_t r[4], uint32_t a) {
    asm volatile("ldmatrix.sync.aligned.m8n8.x4.trans.shared.b16 {%0,%1,%2,%3}, [%4];"
        : "=r"(r[0]), "=r"(r[1]), "=r"(r[2]), "=r"(r[3]) : "r"(a));
}
__device__ __forceinline__ void cpa16(uint32_t s, const void* g) {
    asm volatile("cp.async.cg.shared.global [%0], [%1], 16;"
                 :: "r"(s), "l"(__cvta_generic_to_global(g)) : "memory");
}
#define CP_COMMIT() asm volatile("cp.async.commit_group;" ::: "memory")
#define CP_WAIT2()  asm volatile("cp.async.wait_group 2;" ::: "memory")
#define CP_WAIT1()  asm volatile("cp.async.wait_group 1;" ::: "memory")
#define CP_WAIT0()  asm volatile("cp.async.wait_group 0;" ::: "memory")

// ============================================================================
// Kernel A: fused QKV projection, bf16 tensor cores (unchanged, ~15us).
// ============================================================================
#define QW_PITCH 528
#define OFF_W 0
#define OFF_BIAS 33792
#define OFF_X 34048
#define QKV_SMEM2 50944

__global__ __launch_bounds__(256) void qkv_kernel(
    const float* __restrict__ x,
    const float* __restrict__ Wq, const float* __restrict__ bq,
    const float* __restrict__ Wk, const float* __restrict__ bk,
    const float* __restrict__ Wv, const float* __restrict__ bv)
{
    extern __shared__ char sm[];
    const uint32_t sb = smem_u32(sm);
    const int b = blockIdx.z;
    const int oc0 = blockIdx.y * 64;
    const int n0 = blockIdx.x * 256;
    const int t = threadIdx.x, wid = t >> 5, lane = t & 31;
    const int wOC = wid & 1, wN = wid >> 1;
    const int r = lane >> 2, tq = lane & 3;

    #pragma unroll
    for (int l = 0; l < 16; l++) {
        int idx = t + l * 256;
        int row = idx >> 6, c4 = idx & 63;
        const float* src;
        if (oc0 == 0) src = (row < 32) ? &Wq[row * 256 + c4 * 4]
                                       : &Wk[(row - 32) * 256 + c4 * 4];
        else          src = &Wv[(oc0 - 64 + row) * 256 + c4 * 4];
        float4 w = *(const float4*)src;
        *(uint2*)(sm + OFF_W + row * QW_PITCH + c4 * 8) =
            make_uint2(pack_bf16(w.y, w.x), pack_bf16(w.w, w.z));
    }
    if (t < 64) {
        float bias;
        if (oc0 == 0) bias = (t < 32) ? bq[t] : bk[t - 32];
        else          bias = bv[oc0 - 64 + t];
        ((float*)(sm + OFF_BIAS))[t] = bias;
    }

    float acc[2][8][4];
    #pragma unroll
    for (int m = 0; m < 2; m++)
        #pragma unroll
        for (int j = 0; j < 8; j++)
            #pragma unroll
            for (int q = 0; q < 4; q++) acc[m][j][q] = 0.f;

    float4 xr[8];
    #pragma unroll
    for (int l = 0; l < 8; l++) {
        int idx = t + l * 256;
        int cc = idx >> 6, n4 = idx & 63;
        xr[l] = *(const float4*)&x[(b * NC + cc) * NHW + n0 + n4 * 4];
    }

    for (int ch = 0; ch < 8; ch++) {
        __syncthreads();
        #pragma unroll
        for (int l = 0; l < 8; l++) {
            int idx = t + l * 256;
            int cc = idx >> 6, n4 = idx & 63;
            *(uint2*)(sm + OFF_X + cc * QW_PITCH + n4 * 8) =
                make_uint2(pack_bf16(xr[l].y, xr[l].x), pack_bf16(xr[l].w, xr[l].z));
        }
        __syncthreads();
        if (ch + 1 < 8) {
            int c0n = (ch + 1) * 32;
            #pragma unroll
            for (int l = 0; l < 8; l++) {
                int idx = t + l * 256;
                int cc = idx >> 6, n4 = idx & 63;
                xr[l] = *(const float4*)&x[(b * NC + c0n + cc) * NHW + n0 + n4 * 4];
            }
        }
        #pragma unroll
        for (int ks = 0; ks < 2; ks++) {
            const int cb = ks * 16;
            uint32_t a0[4], a1[4];
            uint32_t wadr = sb + OFF_W + (wOC * 32 + (lane & 15)) * QW_PITCH
                            + (ch * 32 + cb) * 2 + (lane >> 4) * 16;
            ldmx4(a0, wadr);
            ldmx4(a1, wadr + 16 * QW_PITCH);
            uint32_t bt[4][4];
            #pragma unroll
            for (int nb = 0; nb < 4; nb++) {
                uint32_t xadr = sb + OFF_X
                    + (cb + (lane & 7) + ((lane >> 3) & 1) * 8) * QW_PITCH
                    + (wN * 64 + nb * 16 + (lane >> 4) * 8) * 2;
                ldmx4t(bt[nb], xadr);
            }
            #pragma unroll
            for (int nb = 0; nb < 4; nb++) {
                mma_bf16(acc[0][nb * 2],     a0, bt[nb][0], bt[nb][1]);
                mma_bf16(acc[0][nb * 2 + 1], a0, bt[nb][2], bt[nb][3]);
                mma_bf16(acc[1][nb * 2],     a1, bt[nb][0], bt[nb][1]);
                mma_bf16(acc[1][nb * 2 + 1], a1, bt[nb][2], bt[nb][3]);
            }
        }
    }
    __syncthreads();

    const float* bs = (const float*)(sm + OFF_BIAS);
    float bm[2][2];
    bm[0][0] = bs[wOC * 32 + r];      bm[0][1] = bs[wOC * 32 + r + 8];
    bm[1][0] = bs[wOC * 32 + 16 + r]; bm[1][1] = bs[wOC * 32 + 16 + r + 8];
    __syncthreads();

    if (oc0 == 0) {
        const float scl = (wOC == 0) ? 1.4426950408889634f : 1.0f;
        #pragma unroll
        for (int m = 0; m < 2; m++) {
            int oc_r0 = wOC * 32 + m * 16 + r;
            #pragma unroll
            for (int j = 0; j < 8; j++) {
                int n_ = wN * 64 + j * 8 + tq * 2;
                *(__nv_bfloat16*)(sm + n_ * 144 + oc_r0 * 2) =
                    __float2bfloat16((acc[m][j][0] + bm[m][0]) * scl);
                *(__nv_bfloat16*)(sm + (n_ + 1) * 144 + oc_r0 * 2) =
                    __float2bfloat16((acc[m][j][1] + bm[m][0]) * scl);
                *(__nv_bfloat16*)(sm + n_ * 144 + (oc_r0 + 8) * 2) =
                    __float2bfloat16((acc[m][j][2] + bm[m][1]) * scl);
                *(__nv_bfloat16*)(sm + (n_ + 1) * 144 + (oc_r0 + 8) * 2) =
                    __float2bfloat16((acc[m][j][3] + bm[m][1]) * scl);
            }
        }
        __syncthreads();
        #pragma unroll
        for (int l = 0; l < 4; l++) {
            int idx = t + l * 256;
            int nn = idx >> 2, c4 = idx & 3;
            *(float4*)&g_Qb[b][n0 + nn][c4 * 8] =
                *(const float4*)(sm + nn * 144 + c4 * 16);
            *(float4*)&g_Kb[b][n0 + nn][c4 * 8] =
                *(const float4*)(sm + nn * 144 + 64 + c4 * 16);
        }
    } else {
        #pragma unroll
        for (int m = 0; m < 2; m++) {
            int row0 = wOC * 32 + m * 16 + r;
            #pragma unroll
            for (int j = 0; j < 8; j++) {
                int n_ = wN * 64 + j * 8 + tq * 2;
                *(uint32_t*)(sm + row0 * 528 + n_ * 2) =
                    pack_bf16(acc[m][j][1] + bm[m][0], acc[m][j][0] + bm[m][0]);
                *(uint32_t*)(sm + (row0 + 8) * 528 + n_ * 2) =
                    pack_bf16(acc[m][j][3] + bm[m][1], acc[m][j][2] + bm[m][1]);
            }
        }
        __syncthreads();
        #pragma unroll
        for (int l = 0; l < 8; l++) {
            int idx = t + l * 256;
            int row = idx >> 5, n16 = idx & 31;
            *(float4*)&g_Vb[b][oc0 - 64 + row][n0 + n16 * 8] =
                *(const float4*)(sm + row * 528 + n16 * 16);
        }
    }
}

// ============================================================================
// Kernel B: flash attention, key-split P-exchange with 2x4 warp retile.
// CTA 64q x 128E, 8 warps = 2 wM (32 q-rows) x 4 wE (32 E-cols).
// At iter i each warp:
//   - QK+exp+pack its 32 rows x 16-key quarter of tile i+1 (8 MMAs, 16 exp),
//     STS 2 A-frag slots (m16-group, kstep=wE) to pbuf[(i+1)&1];
//   - PV(i): LDS all 8 A-frag slots for its rows, 32 MMAs over its 32 E-cols.
// V read redundancy 4x -> 2x; K-ldmx halved. Pipeline identical to R12.
// ============================================================================
#define OFF_Q 0
#define OFF_K 5120             // 3 x 5120
#define OFF_V 20480            // 3 x 18432
#define OFF_PB 75776           // 2 x 8192 (4 m16 x 4 kstep x 32 lanes x 16B)
#define OFF_SUM 92160          // 4 x 64 f32
#define ATTN_SMEM_B 93184

__global__ __launch_bounds__(256, 2) void attn_kernel(
    const float* __restrict__ x,
    const float* __restrict__ gamma_p,
    float* __restrict__ out)
{
    extern __shared__ char smem[];
    const uint32_t sb = smem_u32(smem);
    const int t = threadIdx.x, wid = t >> 5, lane = t & 31;
    const int b = blockIdx.z;
    const int n0 = blockIdx.x * 64;
    const int e0 = blockIdx.y * 128;
    const int wM = wid & 1, wE = wid >> 1;   // 2 x 4
    const int r = lane >> 2, tq = lane & 3;

    const int krow = t >> 2, kch = t & 3;

    // ---- prologue: G0={Q,K0}  G1={V0,K1}  G2={V1} ----
    cpa16(sb + OFF_Q + krow * 80 + kch * 16, &g_Qb[b][n0 + krow][kch * 8]);
    cpa16(sb + OFF_K + krow * 80 + kch * 16, &g_Kb[b][krow][kch * 8]);
    CP_COMMIT();
    #pragma unroll
    for (int l = 0; l < 4; l++) {
        int c = t + l * 256;
        int e = c >> 3, ch8 = c & 7;
        cpa16(sb + OFF_V + e * 144 + ch8 * 16, &g_Vb[b][e0 + e][ch8 * 8]);
    }
    cpa16(sb + OFF_K + 5120 + krow * 80 + kch * 16, &g_Kb[b][64 + krow][kch * 8]);
    CP_COMMIT();
    #pragma unroll
    for (int l = 0; l < 4; l++) {
        int c = t + l * 256;
        int e = c >> 3, ch8 = c & 7;
        cpa16(sb + OFF_V + 18432 + e * 144 + ch8 * 16, &g_Vb[b][e0 + e][64 + ch8 * 8]);
    }
    CP_COMMIT();

    CP_WAIT2();                  // G0 done: Q + K0 resident
    __syncthreads();

    // persistent Q fragments for 32 rows: qa[m16 half][kstep]
    uint32_t qa[2][2][4];
    #pragma unroll
    for (int m = 0; m < 2; m++) {
        uint32_t qaddr = sb + OFF_Q + (wM * 32 + m * 16 + (lane & 15)) * 80
                         + (lane >> 4) * 16;
        ldmx4(qa[m][0], qaddr);
        ldmx4(qa[m][1], qaddr + 32);
    }
    const uint32_t k_off = (lane & 7) * 80 + (lane >> 3) * 16;
    const uint32_t v_off = (wE * 32 + (lane & 7)) * 144 + (lane >> 3) * 16;
    const uint32_t px_lane = (uint32_t)lane * 16;

    float o[2][4][4];            // [m16 half][eb 8-col group][frag]
    #pragma unroll
    for (int m = 0; m < 2; m++)
        #pragma unroll
        for (int eb = 0; eb < 4; eb++)
            #pragma unroll
            for (int j = 0; j < 4; j++) o[m][eb][j] = 0.f;
    float sums_r[2][2] = {{0.f, 0.f}, {0.f, 0.f}};   // [m][row r / r+8]

    // ---- compute P(J) for own 32 rows x 16-key quarter, publish ----
    #define COMPUTE_P_HALF(J)                                                     \
    {                                                                             \
        const uint32_t kb_ = sb + OFF_K + ((J) % 3) * 5120;                       \
        const uint32_t pb_ = sb + OFF_PB + ((J) & 1) * 8192;                      \
        float c_[2][2][4];                                                        \
        _Pragma("unroll")                                                         \
        for (int g = 0; g < 2; g++) {                                             \
            uint32_t kf[4];                                                       \
            ldmx4(kf, kb_ + (wE * 16 + g * 8) * 80 + k_off);                      \
            _Pragma("unroll")                                                     \
            for (int m = 0; m < 2; m++) {                                         \
                c_[m][g][0] = c_[m][g][1] = c_[m][g][2] = c_[m][g][3] = 0.f;      \
                mma_bf16(c_[m][g], qa[m][0], kf[0], kf[1]);                       \
                mma_bf16(c_[m][g], qa[m][1], kf[2], kf[3]);                       \
            }                                                                     \
        }                                                                         \
        _Pragma("unroll")                                                         \
        for (int m = 0; m < 2; m++) {                                             \
            float p0 = fexp2(c_[m][0][0]), p1 = fexp2(c_[m][0][1]);               \
            float p2 = fexp2(c_[m][0][2]), p3 = fexp2(c_[m][0][3]);               \
            float q0 = fexp2(c_[m][1][0]), q1 = fexp2(c_[m][1][1]);               \
            float q2 = fexp2(c_[m][1][2]), q3 = fexp2(c_[m][1][3]);               \
            sums_r[m][0] += p0 + p1 + q0 + q1;                                    \
            sums_r[m][1] += p2 + p3 + q2 + q3;                                    \
            *(uint4*)((char*)smem + (pb_ - sb)                                    \
                      + (((wM * 2 + m) * 4 + wE) * 32) * 16 + px_lane) =          \
                make_uint4(pack_bf16(p1, p0), pack_bf16(p3, p2),                  \
                           pack_bf16(q1, q0), pack_bf16(q3, q2));                 \
        }                                                                         \
    }

    COMPUTE_P_HALF(0);

    for (int i = 0; i < 64; i++) {
        if (i < 63) { CP_WAIT1(); } else { CP_WAIT0(); }
        __syncthreads();               // V(i)+K(i+1) ready; P(i) exchange visible

        if (i + 2 < 64) {              // prefetch tile i+2: K group, then V group
            int m0 = (i + 2) * 64;
            cpa16(sb + OFF_K + ((i + 2) % 3) * 5120 + krow * 80 + kch * 16,
                  &g_Kb[b][m0 + krow][kch * 8]);
            CP_COMMIT();
            uint32_t vst = sb + OFF_V + ((i + 2) % 3) * 18432;
            #pragma unroll
            for (int l = 0; l < 4; l++) {
                int c = t + l * 256;
                int e = c >> 3, ch8 = c & 7;
                cpa16(vst + e * 144 + ch8 * 16, &g_Vb[b][e0 + e][m0 + ch8 * 8]);
            }
            CP_COMMIT();
        }

        if (i + 1 < 64) COMPUTE_P_HALF(i + 1);

        // ---- PV(i): A-frags from pbuf[i&1], V frags from ring slot i%3 ----
        const uint32_t vb = sb + OFF_V + (i % 3) * 18432;
        const uint32_t pb = sb + OFF_PB + (i & 1) * 8192;
        #pragma unroll
        for (int kp = 0; kp < 2; kp++) {           // 32-key halves
            uint32_t pau[2][2][4];                 // [m][kstep within pair]
            #pragma unroll
            for (int m = 0; m < 2; m++)
                #pragma unroll
                for (int s = 0; s < 2; s++) {
                    uint4 u = *(const uint4*)((char*)smem + OFF_PB + (i & 1) * 8192
                              + (((wM * 2 + m) * 4 + kp * 2 + s) * 32) * 16 + px_lane);
                    pau[m][s][0] = u.x; pau[m][s][1] = u.y;
                    pau[m][s][2] = u.z; pau[m][s][3] = u.w;
                }
            #pragma unroll
            for (int eb = 0; eb < 4; eb++) {
                uint32_t v[4];
                ldmx4(v, vb + v_off + eb * 1152 + kp * 64);
                #pragma unroll
                for (int m = 0; m < 2; m++) {
                    mma_bf16(o[m][eb], pau[m][0], v[0], v[1]);
                    mma_bf16(o[m][eb], pau[m][1], v[2], v[3]);
                }
            }
        }
        (void)pb;
    }

    // ---- merge rowsum quarters across the 4 wE warps ----
    #pragma unroll
    for (int m = 0; m < 2; m++)
        #pragma unroll
        for (int h = 0; h < 2; h++) {
            sums_r[m][h] += __shfl_xor_sync(0xffffffffu, sums_r[m][h], 1);
            sums_r[m][h] += __shfl_xor_sync(0xffffffffu, sums_r[m][h], 2);
        }
    float* sums = (float*)(smem + OFF_SUM);   // [4 wE][64 rows]
    __syncthreads();
    if (tq == 0) {
        #pragma unroll
        for (int m = 0; m < 2; m++)
            #pragma unroll
            for (int h = 0; h < 2; h++)
                sums[wE * 64 + wM * 32 + m * 16 + h * 8 + r] = sums_r[m][h];
    }
    __syncthreads();
    const float g = gamma_p[0];
    float scl[2][2];
    #pragma unroll
    for (int m = 0; m < 2; m++)
        #pragma unroll
        for (int h = 0; h < 2; h++) {
            int row = wM * 32 + m * 16 + h * 8 + r;
            scl[m][h] = g / (sums[row] + sums[64 + row] + sums[128 + row]
                             + sums[192 + row]);
        }

    __syncthreads();
    float* os = (float*)smem;                 // [64][133]
    #pragma unroll
    for (int m = 0; m < 2; m++)
        #pragma unroll
        for (int eb = 0; eb < 4; eb++) {
            int e = wE * 32 + eb * 8 + 2 * tq;
            int row0 = wM * 32 + m * 16 + r;
            os[row0 * 133 + e]           = o[m][eb][0] * scl[m][0];
            os[row0 * 133 + e + 1]       = o[m][eb][1] * scl[m][0];
            os[(row0 + 8) * 133 + e]     = o[m][eb][2] * scl[m][1];
            os[(row0 + 8) * 133 + e + 1] = o[m][eb][3] * scl[m][1];
        }
    __syncthreads();
    #pragma unroll 8
    for (int l = 0; l < 32; l++) {
        int idx = t + l * 256;
        int n = idx & 63, e = idx >> 6;
        int gi = (b * NC + e0 + e) * NHW + n0 + n;
        out[gi] = os[n * 133 + e] + x[gi];
    }
}

// ============================================================================
extern "C" void kernel_launch(void* const* d_in, const int* in_sizes, int n_in,
                              void* d_out, int out_size) {
    (void)in_sizes; (void)n_in; (void)out_size;
    const float* x     = (const float*)d_in[0];
    const float* Wq    = (const float*)d_in[1];
    const float* bq    = (const float*)d_in[2];
    const float* Wk    = (const float*)d_in[3];
    const float* bk    = (const float*)d_in[4];
    const float* Wv    = (const float*)d_in[5];
    const float* bv    = (const float*)d_in[6];
    const float* gamma = (const float*)d_in[7];
    float* out = (float*)d_out;

    cudaFuncSetAttribute(qkv_kernel,
                         cudaFuncAttributeMaxDynamicSharedMemorySize, QKV_SMEM2);
    cudaFuncSetAttribute(attn_kernel,
                         cudaFuncAttributeMaxDynamicSharedMemorySize, ATTN_SMEM_B);

    dim3 gA(16, 5, NB);
    qkv_kernel<<<gA, 256, QKV_SMEM2>>>(x, Wq, bq, Wk, bk, Wv, bv);

    dim3 gB(64, 2, NB);
    attn_kernel<<<gB, 256, ATTN_SMEM_B>>>(x, gamma, out);
}